// round 8
// baseline (speedup 1.0000x reference)
#include <cuda_runtime.h>
#include <cstdint>

// SignalDualBackground: out[b,c,s,t] = (1 - spikes[b,c,s,t]) * stat[b,c,t]
//   x[b,c,t]  = mean_s spikes[b,c,s,t]            (S=64)
//   stat[.,t] = beta*stat[.,t-1] + (1-beta)*x[.,t], stat[.,-1]=0  (T=1024)
//
// R8 = R7 (cluster-2 shared tile, symmetric exchange + redundant scan,
// one cluster barrier, ideal 1.02GB traffic) + SMEM TILE CACHE:
// each thread caches 5 of its 8 rows in shared memory during phase 1, so
// phase 3 reads 5/8 from smem (128B/cyc/SM) and only 3/8 from L2. Cuts
// ~320MB of LTS read-hit traffic and shortens the non-DRAM phase-3 window;
// cached rows use __ldcs in phase 1 (never re-read), uncached rows default
// policy (L2 footprint shrinks to ~14MB chip-wide).

#define T_DIM 1024
#define S_DIM 64
#define THREADS 1024
#define T4 (T_DIM / 4)              // 256 float4 per row
#define ROWS_PER_CTA 32
#define ROWS_PER_THREAD 8           // 32 rows / 4 parts
#define CACHE_ROWS 5                // rows per thread held in smem
#define TILE_F4 (S_DIM * T4)        // 16384 float4 per tile

// dynamic smem layout (bytes)
#define SM_CACHE_OFF 0
#define SM_CACHE_SZ  (4 * CACHE_ROWS * T4 * 16)   // 20 row-slots *256 *16B = 80KB
#define SM_RED_OFF   (SM_CACHE_OFF + SM_CACHE_SZ) // 16KB
#define SM_RED_SZ    (THREADS * 16)
#define SM_STAT_OFF  (SM_RED_OFF + SM_RED_SZ)     // 4KB
#define SM_STAT_SZ   (T4 * 16)
#define SM_PEER_OFF  (SM_STAT_OFF + SM_STAT_SZ)   // 4KB
#define SM_PEER_SZ   (T4 * 16)
#define SM_MA_OFF    (SM_PEER_OFF + SM_PEER_SZ)   // 64B
#define SM_TOTAL     (SM_MA_OFF + 64)

__device__ __forceinline__ uint32_t smem_u32(const void* p) {
    uint32_t a;
    asm("{ .reg .u64 t; cvta.to.shared.u64 t, %1; cvt.u32.u64 %0, t; }"
        : "=r"(a) : "l"(p));
    return a;
}

__global__ __launch_bounds__(THREADS, 2) __cluster_dims__(2, 1, 1)
void sdb_kernel(const float4* __restrict__ sp,
                const float* __restrict__ beta_p,
                float4* __restrict__ out) {
    extern __shared__ unsigned char dsm[];
    float4* cache = (float4*)(dsm + SM_CACHE_OFF);
    float4* red   = (float4*)(dsm + SM_RED_OFF);
    float4* statS = (float4*)(dsm + SM_STAT_OFF);
    float4* peerS = (float4*)(dsm + SM_PEER_OFF);
    float*  Ms    = (float*)(dsm + SM_MA_OFF);
    float*  As    = Ms + 8;

    const int tid  = threadIdx.x;
    const int col  = tid & (T4 - 1);  // 0..255 time chunk
    const int part = tid >> 8;        // 0..3
    const int lane = tid & 31;
    const int wid  = tid >> 5;        // part0 -> 0..7

    const int rank = (int)(blockIdx.x & 1);      // ctarank within cluster
    const int peer = rank ^ 1;
    const size_t base = (size_t)(blockIdx.x >> 1) * TILE_F4;
    const int srow0 = rank * ROWS_PER_CTA + part * ROWS_PER_THREAD;

    const float beta = beta_p[0];
    const float omb  = 1.0f - beta;

    // ---------- Phase 1: accumulate 8 rows, cache first 5 in smem ----------
    const float4* p = sp + base + (size_t)srow0 * T4 + col;
    float4* cb = cache + (size_t)(part * CACHE_ROWS) * T4 + col;
    float4 acc0 = make_float4(0.f, 0.f, 0.f, 0.f);
    float4 acc1 = make_float4(0.f, 0.f, 0.f, 0.f);
    #pragma unroll
    for (int k = 0; k < CACHE_ROWS; ++k) {       // cached rows: evict-first
        float4 v = __ldcs(&p[(size_t)k * T4]);
        cb[(size_t)k * T4] = v;
        acc0.x += v.x; acc0.y += v.y; acc0.z += v.z; acc0.w += v.w;
    }
    #pragma unroll
    for (int k = CACHE_ROWS; k < ROWS_PER_THREAD; ++k) {  // stay in L2
        float4 v = p[(size_t)k * T4];
        acc1.x += v.x; acc1.y += v.y; acc1.z += v.z; acc1.w += v.w;
    }
    acc0.x += acc1.x; acc0.y += acc1.y; acc0.z += acc1.z; acc0.w += acc1.w;
    red[tid] = acc0;
    __syncthreads();

    // per-col sum over this CTA's 32 rows (part 0), symmetric DSMEM push
    float4 csum;
    if (part == 0) {
        float4 a4 = red[col];
        float4 b4 = red[col + 256];
        float4 c4 = red[col + 512];
        float4 d4 = red[col + 768];
        csum.x = a4.x + b4.x + c4.x + d4.x;
        csum.y = a4.y + b4.y + c4.y + d4.y;
        csum.z = a4.z + b4.z + c4.z + d4.z;
        csum.w = a4.w + b4.w + c4.w + d4.w;

        uint32_t la = smem_u32(&peerS[col]);
        uint32_t ra;
        asm("mapa.shared::cluster.u32 %0, %1, %2;" : "=r"(ra) : "r"(la), "r"(peer));
        asm volatile("st.shared::cluster.v4.b32 [%0], {%1,%2,%3,%4};"
            :: "r"(ra),
               "r"(__float_as_uint(csum.x)), "r"(__float_as_uint(csum.y)),
               "r"(__float_as_uint(csum.z)), "r"(__float_as_uint(csum.w))
            : "memory");
    }
    // single cluster barrier: peer partials visible on both sides
    asm volatile("barrier.cluster.arrive.aligned;" ::: "memory");
    asm volatile("barrier.cluster.wait.aligned;" ::: "memory");

    // ---------- Phase 2: BOTH ranks compute the scan (redundant) ----------
    if (part == 0) {
        float4 o4 = peerS[col];
        const float inv = 1.0f / (float)S_DIM;
        const float x0 = (csum.x + o4.x) * inv;
        const float x1 = (csum.y + o4.y) * inv;
        const float x2 = (csum.z + o4.z) * inv;
        const float x3 = (csum.w + o4.w) * inv;

        // per-thread composite over 4 time steps: state' = m*state + a
        float a = omb * x0;
        a = beta * a + omb * x1;
        a = beta * a + omb * x2;
        a = beta * a + omb * x3;
        float m = beta * beta;
        m = m * m;                    // beta^4

        #pragma unroll
        for (int d = 1; d < 32; d <<= 1) {
            float ap = __shfl_up_sync(0xffffffffu, a, d);
            float mp = __shfl_up_sync(0xffffffffu, m, d);
            if (lane >= d) { a += m * ap; m *= mp; }
        }
        if (lane == 31) { Ms[wid] = m; As[wid] = a; }
        asm volatile("bar.sync 1, 256;" ::: "memory");  // 8 scan warps only

        float pref = 0.0f;
        #pragma unroll
        for (int w = 0; w < 8; ++w) {
            if (w == wid) break;
            pref = Ms[w] * pref + As[w];
        }
        const float a_full = a + m * pref;
        const float a_prev = __shfl_up_sync(0xffffffffu, a_full, 1);
        const float a_excl = (lane > 0) ? a_prev : pref;

        float st = a_excl;
        st = beta * st + omb * x0; const float r0 = st;
        st = beta * st + omb * x1; const float r1 = st;
        st = beta * st + omb * x2; const float r2 = st;
        st = beta * st + omb * x3; const float r3 = st;
        statS[col] = make_float4(r0, r1, r2, r3);
    }
    __syncthreads();                  // local stat visible to all warps

    // ---------- Phase 3: 5 rows from smem, 3 rows from L2 ----------
    const float4 st4 = statS[col];
    float4* pw = out + base + (size_t)srow0 * T4 + col;
    #pragma unroll
    for (int k = 0; k < CACHE_ROWS; ++k) {
        float4 v = cb[(size_t)k * T4];
        float4 o;
        o.x = (1.0f - v.x) * st4.x;
        o.y = (1.0f - v.y) * st4.y;
        o.z = (1.0f - v.z) * st4.z;
        o.w = (1.0f - v.w) * st4.w;
        __stcs(&pw[(size_t)k * T4], o);
    }
    #pragma unroll
    for (int k = CACHE_ROWS; k < ROWS_PER_THREAD; ++k) {
        float4 v = __ldcs(&p[(size_t)k * T4]);    // L2 hit, last use
        float4 o;
        o.x = (1.0f - v.x) * st4.x;
        o.y = (1.0f - v.y) * st4.y;
        o.z = (1.0f - v.z) * st4.z;
        o.w = (1.0f - v.w) * st4.w;
        __stcs(&pw[(size_t)k * T4], o);
    }
}

extern "C" void kernel_launch(void* const* d_in, const int* in_sizes, int n_in,
                              void* d_out, int out_size) {
    const float* spikes = (const float*)d_in[0];
    const float* beta   = (const float*)d_in[1];
    float* out          = (float*)d_out;

    const int nbc = in_sizes[0] / (S_DIM * T_DIM);  // 2048 tiles

    cudaFuncSetAttribute(sdb_kernel,
                         cudaFuncAttributeMaxDynamicSharedMemorySize, SM_TOTAL);
    // one cluster (2 CTAs) per tile
    sdb_kernel<<<nbc * 2, THREADS, SM_TOTAL>>>(
        (const float4*)spikes, beta, (float4*)out);
}

// round 9
// speedup vs baseline: 1.0915x; 1.0915x over previous
#include <cuda_runtime.h>
#include <cstdint>

// SignalDualBackground: out[b,c,s,t] = (1 - spikes[b,c,s,t]) * stat[b,c,t]
//   x[b,c,t]  = mean_s spikes[b,c,s,t]            (S=64)
//   stat[.,t] = beta*stat[.,t-1] + (1-beta)*x[.,t], stat[.,-1]=0  (T=1024)
//
// R9 = R7 (cluster-2 shared tile, symmetric DSMEM exchange, one cluster
// barrier, ideal 1.02GB traffic) with two bubble cuts:
//  1) ALL 4 parts compute the scan redundantly (each part's 256 threads
//     cover all 256 cols; named barrier per part). Removes barrier B, the
//     statS smem round-trip, and the 24-warp idle during the scan.
//  2) Phase-3 rows 0-1 are prefetched (__ldcs) BEFORE the cluster barrier;
//     their L2 latency hides under the ~490cyc barrier wait.

#define T_DIM 1024
#define S_DIM 64
#define THREADS 1024
#define T4 (T_DIM / 4)              // 256 float4 per row
#define ROWS_PER_CTA 32
#define ROWS_PER_THREAD 8           // 32 rows / 4 parts
#define TILE_F4 (S_DIM * T4)        // 16384 float4 per tile

__device__ __forceinline__ uint32_t smem_u32(const void* p) {
    uint32_t a;
    asm("{ .reg .u64 t; cvta.to.shared.u64 t, %1; cvt.u32.u64 %0, t; }"
        : "=r"(a) : "l"(p));
    return a;
}

__global__ __launch_bounds__(THREADS, 2) __cluster_dims__(2, 1, 1)
void sdb_kernel(const float4* __restrict__ sp,
                const float* __restrict__ beta_p,
                float4* __restrict__ out) {
    __shared__ float4 red[THREADS];   // 16KB: per-thread partials
    __shared__ float4 peerS[T4];      // 4KB: peer's 32-row column sums
    __shared__ float MsA[4][8], AsA[4][8];  // per-part warp aggregates

    const int tid  = threadIdx.x;
    const int col  = tid & (T4 - 1);  // 0..255 time chunk
    const int part = tid >> 8;        // 0..3
    const int lane = tid & 31;
    const int wid8 = (tid >> 5) & 7;  // warp index within part: 0..7

    const int rank = (int)(blockIdx.x & 1);      // ctarank within cluster
    const int peer = rank ^ 1;
    const size_t base = (size_t)(blockIdx.x >> 1) * TILE_F4;
    const int srow0 = rank * ROWS_PER_CTA + part * ROWS_PER_THREAD;

    const float beta = beta_p[0];
    const float omb  = 1.0f - beta;

    // ---------- Phase 1: partial sums over this thread's 8 rows ----------
    const float4* p = sp + base + (size_t)srow0 * T4 + col;
    float4 acc0 = make_float4(0.f, 0.f, 0.f, 0.f);
    float4 acc1 = make_float4(0.f, 0.f, 0.f, 0.f);
    #pragma unroll
    for (int k = 0; k < ROWS_PER_THREAD; k += 2) {
        float4 v0 = p[(size_t)k * T4];
        float4 v1 = p[(size_t)(k + 1) * T4];
        acc0.x += v0.x; acc0.y += v0.y; acc0.z += v0.z; acc0.w += v0.w;
        acc1.x += v1.x; acc1.y += v1.y; acc1.z += v1.z; acc1.w += v1.w;
    }
    acc0.x += acc1.x; acc0.y += acc1.y; acc0.z += acc1.z; acc0.w += acc1.w;
    red[tid] = acc0;
    __syncthreads();                  // barrier A: red[] complete

    // ---------- every part computes the CTA column sum ----------
    float4 a4 = red[col];
    float4 b4 = red[col + 256];
    float4 c4 = red[col + 512];
    float4 d4 = red[col + 768];
    float4 csum;
    csum.x = a4.x + b4.x + c4.x + d4.x;
    csum.y = a4.y + b4.y + c4.y + d4.y;
    csum.z = a4.z + b4.z + c4.z + d4.z;
    csum.w = a4.w + b4.w + c4.w + d4.w;

    // part 0 pushes the CTA sum to the peer's peerS[col] (DSMEM)
    if (part == 0) {
        uint32_t la = smem_u32(&peerS[col]);
        uint32_t ra;
        asm("mapa.shared::cluster.u32 %0, %1, %2;" : "=r"(ra) : "r"(la), "r"(peer));
        asm volatile("st.shared::cluster.v4.b32 [%0], {%1,%2,%3,%4};"
            :: "r"(ra),
               "r"(__float_as_uint(csum.x)), "r"(__float_as_uint(csum.y)),
               "r"(__float_as_uint(csum.z)), "r"(__float_as_uint(csum.w))
            : "memory");
    }

    // prefetch phase-3 rows 0,1 across the barrier (stat-independent)
    float4 pf0 = __ldcs(&p[0]);
    float4 pf1 = __ldcs(&p[T4]);

    // single cluster barrier: peer partials visible on both sides
    asm volatile("barrier.cluster.arrive.aligned;" ::: "memory");
    asm volatile("barrier.cluster.wait.aligned;" ::: "memory");

    // ---------- Phase 2: redundant scan in EVERY part ----------
    float4 o4 = peerS[col];
    const float inv = 1.0f / (float)S_DIM;
    const float x0 = (csum.x + o4.x) * inv;
    const float x1 = (csum.y + o4.y) * inv;
    const float x2 = (csum.z + o4.z) * inv;
    const float x3 = (csum.w + o4.w) * inv;

    // per-thread composite over 4 time steps: state' = m*state + a
    float a = omb * x0;
    a = beta * a + omb * x1;
    a = beta * a + omb * x2;
    a = beta * a + omb * x3;
    float m = beta * beta;
    m = m * m;                        // beta^4

    #pragma unroll
    for (int d = 1; d < 32; d <<= 1) {
        float ap = __shfl_up_sync(0xffffffffu, a, d);
        float mp = __shfl_up_sync(0xffffffffu, m, d);
        if (lane >= d) { a += m * ap; m *= mp; }
    }
    if (lane == 31) { MsA[part][wid8] = m; AsA[part][wid8] = a; }
    // sync the 8 warps of THIS part only (named barrier 1..4)
    asm volatile("bar.sync %0, 256;" :: "r"(part + 1) : "memory");

    float pref = 0.0f;
    #pragma unroll
    for (int w = 0; w < 8; ++w) {
        if (w == wid8) break;
        pref = MsA[part][w] * pref + AsA[part][w];
    }
    const float a_full = a + m * pref;
    const float a_prev = __shfl_up_sync(0xffffffffu, a_full, 1);
    const float a_excl = (lane > 0) ? a_prev : pref;

    float st = a_excl;
    st = beta * st + omb * x0; const float r0 = st;
    st = beta * st + omb * x1; const float r1 = st;
    st = beta * st + omb * x2; const float r2 = st;
    st = beta * st + omb * x3; const float r3 = st;

    // ---------- Phase 3: out = (1-spike)*stat ; re-read hits L2 ----------
    float4* pw = out + base + (size_t)srow0 * T4 + col;
    {
        float4 o;
        o.x = (1.0f - pf0.x) * r0;
        o.y = (1.0f - pf0.y) * r1;
        o.z = (1.0f - pf0.z) * r2;
        o.w = (1.0f - pf0.w) * r3;
        __stcs(&pw[0], o);
        o.x = (1.0f - pf1.x) * r0;
        o.y = (1.0f - pf1.y) * r1;
        o.z = (1.0f - pf1.z) * r2;
        o.w = (1.0f - pf1.w) * r3;
        __stcs(&pw[T4], o);
    }
    #pragma unroll
    for (int k = 2; k < ROWS_PER_THREAD; ++k) {
        float4 v = __ldcs(&p[(size_t)k * T4]);    // L2 hit, last use
        float4 o;
        o.x = (1.0f - v.x) * r0;
        o.y = (1.0f - v.y) * r1;
        o.z = (1.0f - v.z) * r2;
        o.w = (1.0f - v.w) * r3;
        __stcs(&pw[(size_t)k * T4], o);
    }
}

extern "C" void kernel_launch(void* const* d_in, const int* in_sizes, int n_in,
                              void* d_out, int out_size) {
    const float* spikes = (const float*)d_in[0];
    const float* beta   = (const float*)d_in[1];
    float* out          = (float*)d_out;

    const int nbc = in_sizes[0] / (S_DIM * T_DIM);  // 2048 tiles

    // one cluster (2 CTAs) per tile
    sdb_kernel<<<nbc * 2, THREADS>>>(
        (const float4*)spikes, beta, (float4*)out);
}